// round 12
// baseline (speedup 1.0000x reference)
#include <cuda_runtime.h>
#include <cstdint>

// Screen tiling constants (match reference)
#define SW 1280
#define SH 720
#define TL 16
#define NBW 80           // ceil(1280/16)
#define NBH 45           // ceil(720/16)
#define NUM_BLOCK (NBW*NBH)   // 3600
#define N_POINTS 32768

// Precomputed separable masks (bytes 0/1). Static device scratch (no allocs).
__device__ unsigned char g_maskX[NBW * N_POINTS];   // 2.62 MB
__device__ unsigned char g_maskY[NBH * N_POINTS];   // 1.47 MB

// ---------------------------------------------------------------------------
// Phase 1: per point, compute clamped AABB -> tile index ranges, then write
// one byte per (tile-row/col, point). Coalesced across threads per row.
// ---------------------------------------------------------------------------
__global__ void build_masks_kernel(const float* __restrict__ pos2d,
                                   const float* __restrict__ radius)
{
    int n = blockIdx.x * blockDim.x + threadIdx.x;
    if (n >= N_POINTS) return;

    float px = pos2d[2 * n + 0];
    float py = pos2d[2 * n + 1];
    float r  = radius[n];

    // Match reference exactly: clip to [0, W]/[0, H] then truncate to int32.
    int xmin = (int)fminf(fmaxf(px - r, 0.0f), (float)SW);
    int xmax = (int)fminf(fmaxf(px + r, 0.0f), (float)SW);
    int ymin = (int)fminf(fmaxf(py - r, 0.0f), (float)SH);
    int ymax = (int)fminf(fmaxf(py + r, 0.0f), (float)SH);

    // Tile edges are exact multiples of 16 (no screen-edge clamping needed):
    //   in_mask <=> xi in [xmin>>4, (xmax+15)>>4)   when xmax > xmin
    int x0 = xmin >> 4;
    int x1 = (xmax + 15) >> 4;
    if (xmax <= xmin) x1 = x0;          // degenerate AABB -> empty
    int y0 = ymin >> 4;
    int y1 = (ymax + 15) >> 4;
    if (ymax <= ymin) y1 = y0;

    #pragma unroll
    for (int xi = 0; xi < NBW; xi++)
        g_maskX[xi * N_POINTS + n] = (unsigned char)((xi >= x0) & (xi < x1));

    #pragma unroll
    for (int yi = 0; yi < NBH; yi++)
        g_maskY[yi * N_POINTS + n] = (unsigned char)((yi >= y0) & (yi < y1));
}

// ---------------------------------------------------------------------------
// Phase 2: out[t*N + n] = float(maskX[t/45][n] & maskY[t%45][n]).
// 8 points per thread. Mask bytes (0/1) are expanded straight to the f32 bit
// pattern: PRMT extracts byte k, IMAD multiplies by 0x3f800000 -> 0x3f800000
// (1.0f) or 0x00000000 (0.0f). No I2F, no FP pipe. Two uint4 .cs streaming
// stores keep the 472 MB write stream from evicting the 4 MB hot masks.
// grid = (32768/(256*8)=16, 3600), block = 256.
// ---------------------------------------------------------------------------
__global__ void __launch_bounds__(256, 8)
expand_kernel(uint4* __restrict__ out)
{
    int t  = blockIdx.y;                      // tile id, 0..3599
    int n8 = (blockIdx.x * blockDim.x + threadIdx.x) * 8;

    int xi = t / NBH;
    int yi = t - xi * NBH;

    uint2 a = __ldg(reinterpret_cast<const uint2*>(&g_maskX[xi * N_POINTS + n8]));
    uint2 b = __ldg(reinterpret_cast<const uint2*>(&g_maskY[yi * N_POINTS + n8]));
    unsigned int m0 = a.x & b.x;              // 4 bytes, each 0x00/0x01
    unsigned int m1 = a.y & b.y;

    const unsigned int ONE = 0x3f800000u;     // bit pattern of 1.0f

    uint4 o0, o1;
    o0.x = __byte_perm(m0, 0u, 0x4440) * ONE;
    o0.y = __byte_perm(m0, 0u, 0x4441) * ONE;
    o0.z = __byte_perm(m0, 0u, 0x4442) * ONE;
    o0.w = __byte_perm(m0, 0u, 0x4443) * ONE;
    o1.x = __byte_perm(m1, 0u, 0x4440) * ONE;
    o1.y = __byte_perm(m1, 0u, 0x4441) * ONE;
    o1.z = __byte_perm(m1, 0u, 0x4442) * ONE;
    o1.w = __byte_perm(m1, 0u, 0x4443) * ONE;

    // uint4 index: (t*N_POINTS + n8) floats / 4 floats-per-uint4
    size_t idx = ((size_t)t * N_POINTS + n8) >> 2;
    __stcs(out + idx,     o0);
    __stcs(out + idx + 1, o1);
}

extern "C" void kernel_launch(void* const* d_in, const int* in_sizes, int n_in,
                              void* d_out, int out_size)
{
    const float* pos2d  = (const float*)d_in[0];
    const float* radius = (const float*)d_in[1];
    uint4* out          = (uint4*)d_out;

    build_masks_kernel<<<(N_POINTS + 255) / 256, 256>>>(pos2d, radius);

    dim3 grid(N_POINTS / (256 * 8), NUM_BLOCK);   // (16, 3600)
    expand_kernel<<<grid, 256>>>(out);
}

// round 13
// speedup vs baseline: 1.6229x; 1.6229x over previous
#include <cuda_runtime.h>
#include <cstdint>

// Screen tiling constants (match reference)
#define SW 1280
#define SH 720
#define TL 16
#define NBW 80           // ceil(1280/16)
#define NBH 45           // ceil(720/16)
#define NUM_BLOCK (NBW*NBH)   // 3600
#define N_POINTS 32768

// Precomputed separable masks (bytes 0/1). Static device scratch (no allocs).
__device__ unsigned char g_maskX[NBW * N_POINTS];   // 2.62 MB
__device__ unsigned char g_maskY[NBH * N_POINTS];   // 1.47 MB

// ---------------------------------------------------------------------------
// Phase 1: per point, compute clamped AABB -> tile index ranges, then write
// one byte per (tile-row/col, point). Coalesced across threads per row.
// ---------------------------------------------------------------------------
__global__ void build_masks_kernel(const float* __restrict__ pos2d,
                                   const float* __restrict__ radius)
{
    int n = blockIdx.x * blockDim.x + threadIdx.x;
    if (n >= N_POINTS) return;

    float px = pos2d[2 * n + 0];
    float py = pos2d[2 * n + 1];
    float r  = radius[n];

    // Match reference exactly: clip to [0, W]/[0, H] then truncate to int32.
    int xmin = (int)fminf(fmaxf(px - r, 0.0f), (float)SW);
    int xmax = (int)fminf(fmaxf(px + r, 0.0f), (float)SW);
    int ymin = (int)fminf(fmaxf(py - r, 0.0f), (float)SH);
    int ymax = (int)fminf(fmaxf(py + r, 0.0f), (float)SH);

    // Tile edges are exact multiples of 16 (no screen-edge clamping needed):
    //   in_mask <=> xi in [xmin>>4, (xmax+15)>>4)   when xmax > xmin
    int x0 = xmin >> 4;
    int x1 = (xmax + 15) >> 4;
    if (xmax <= xmin) x1 = x0;          // degenerate AABB -> empty
    int y0 = ymin >> 4;
    int y1 = (ymax + 15) >> 4;
    if (ymax <= ymin) y1 = y0;

    #pragma unroll
    for (int xi = 0; xi < NBW; xi++)
        g_maskX[xi * N_POINTS + n] = (unsigned char)((xi >= x0) & (xi < x1));

    #pragma unroll
    for (int yi = 0; yi < NBH; yi++)
        g_maskY[yi * N_POINTS + n] = (unsigned char)((yi >= y0) & (yi < y1));
}

// ---------------------------------------------------------------------------
// Phase 2: out[t*N + n] = float(maskX[t/45][n] & maskY[t%45][n]).
// 8 points per thread, as TWO WARP-CONTIGUOUS groups of 4: thread tid handles
// n_a = blockBase + tid*4 and n_b = n_a + 1024 (= blockDim*4). Each STG.128
// across a warp is a contiguous 512 B span (4x128B sectors) — R12's
// interleaved layout (stride-32B, 8 lines/store) made L1 wavefronts the
// bottleneck (L1=80.4%, DRAM=48%). Unpack stays PRMT+IMAD: byte k -> f32 bit
// pattern 0x3f800000*k, no I2F. .cs stores keep the 472 MB stream from
// evicting the 4 MB hot masks.
// grid = (32768/(256*8)=16, 3600), block = 256.
// ---------------------------------------------------------------------------
__global__ void __launch_bounds__(256, 8)
expand_kernel(uint4* __restrict__ out)
{
    const int t   = blockIdx.y;               // tile id, 0..3599
    const int tid = threadIdx.x;
    const int blockBase = blockIdx.x * (256 * 8);        // first point of block
    const int n_a = blockBase + tid * 4;                 // group A point index
    const int n_b = n_a + 256 * 4;                       // group B, +1024 pts

    int xi = t / NBH;
    int yi = t - xi * NBH;
    const unsigned char* mx = &g_maskX[xi * N_POINTS];
    const unsigned char* my = &g_maskY[yi * N_POINTS];

    unsigned int a0 = __ldg(reinterpret_cast<const unsigned int*>(mx + n_a));
    unsigned int b0 = __ldg(reinterpret_cast<const unsigned int*>(my + n_a));
    unsigned int a1 = __ldg(reinterpret_cast<const unsigned int*>(mx + n_b));
    unsigned int b1 = __ldg(reinterpret_cast<const unsigned int*>(my + n_b));
    unsigned int m0 = a0 & b0;                // 4 bytes, each 0x00/0x01
    unsigned int m1 = a1 & b1;

    const unsigned int ONE = 0x3f800000u;     // bit pattern of 1.0f

    uint4 o0, o1;
    o0.x = __byte_perm(m0, 0u, 0x4440) * ONE;
    o0.y = __byte_perm(m0, 0u, 0x4441) * ONE;
    o0.z = __byte_perm(m0, 0u, 0x4442) * ONE;
    o0.w = __byte_perm(m0, 0u, 0x4443) * ONE;
    o1.x = __byte_perm(m1, 0u, 0x4440) * ONE;
    o1.y = __byte_perm(m1, 0u, 0x4441) * ONE;
    o1.z = __byte_perm(m1, 0u, 0x4442) * ONE;
    o1.w = __byte_perm(m1, 0u, 0x4443) * ONE;

    // uint4 index: (t*N_POINTS + n) floats / 4 floats-per-uint4
    const size_t rowBase = (size_t)t * (N_POINTS / 4);
    __stcs(out + rowBase + (n_a >> 2), o0);   // warp-contiguous 512 B
    __stcs(out + rowBase + (n_b >> 2), o1);   // warp-contiguous 512 B
}

extern "C" void kernel_launch(void* const* d_in, const int* in_sizes, int n_in,
                              void* d_out, int out_size)
{
    const float* pos2d  = (const float*)d_in[0];
    const float* radius = (const float*)d_in[1];
    uint4* out          = (uint4*)d_out;

    build_masks_kernel<<<(N_POINTS + 255) / 256, 256>>>(pos2d, radius);

    dim3 grid(N_POINTS / (256 * 8), NUM_BLOCK);   // (16, 3600)
    expand_kernel<<<grid, 256>>>(out);
}